// round 13
// baseline (speedup 1.0000x reference)
#include <cuda_runtime.h>
#include <math.h>

#define NPRI  10647
#define BB    16
#define LL    50
#define NCLS  80
#define BLKS_PER_B 45      // lvl0: 3 blocks, lvl1: 9, lvl2: 33 (cell-contiguous per anchor)
#define SUPPW_PER_B 339    // 3*(6+22+85) words, segments padded per (lvl,a)
#define TT 512             // k_targets block size
#define CH 21              // ceil(10647/512)

// ---------------- compile-time priors (double math -> f32, matches numpy) ----
struct alignas(16) Priors {
    float aux[NPRI][4];   // col(j), row(i), aw_pix, ah_pix  (winner decode only)
};

constexpr Priors mk_priors() {
    Priors t{};
    const int AW[3][3] = {{116, 156, 373}, {30, 62, 59}, {10, 16, 33}};
    const int AH[3][3] = {{90, 198, 326}, {61, 45, 119}, {13, 30, 23}};
    const int SSv[3] = {13, 26, 52};
    int n = 0;
    for (int l = 0; l < 3; l++) {
        int S = SSv[l];
        for (int i = 0; i < S; i++)
            for (int j = 0; j < S; j++)
                for (int a = 0; a < 3; a++) {
                    t.aux[n][0] = (float)j;
                    t.aux[n][1] = (float)i;
                    t.aux[n][2] = (float)AW[l][a];
                    t.aux[n][3] = (float)AH[l][a];
                    n++;
                }
    }
    return t;
}
__device__ constexpr Priors g_P = mk_priors();

// factored prior geometry: px/py per (lvl*3+a, j), pw/ph/area per (lvl*3+a)
struct PriorTabs {
    float PX[9][52];   // cx - 0.5*w  (f64 math -> f32, matches numpy bits)
    float PY[9][52];   // cy - 0.5*h
    float PW[9];
    float PH[9];
    float AREA[9];     // f32(w)*f32(h) == __fmul_rn(pw, ph)
};

constexpr PriorTabs mk_tabs() {
    PriorTabs t{};
    const int AW[3][3] = {{116, 156, 373}, {30, 62, 59}, {10, 16, 33}};
    const int AH[3][3] = {{90, 198, 326}, {61, 45, 119}, {13, 30, 23}};
    const int SSv[3] = {13, 26, 52};
    for (int l = 0; l < 3; l++) {
        int S = SSv[l];
        for (int a = 0; a < 3; a++) {
            int la = l * 3 + a;
            double w = AW[l][a] / 416.0;
            double h = AH[l][a] / 416.0;
            t.PW[la] = (float)w;
            t.PH[la] = (float)h;
            t.AREA[la] = (float)w * (float)h;
            for (int j = 0; j < S; j++) {
                t.PX[la][j] = (float)((j + 0.5) / (double)S - 0.5 * w);
                t.PY[la][j] = (float)((j + 0.5) / (double)S - 0.5 * h);
            }
        }
    }
    return t;
}
__device__ constexpr PriorTabs g_T = mk_tabs();

// ---------------- compact cross-kernel state -------------------------------
__device__ int      g_idx[BB * LL];            // chosen prior per (b,label), -1 invalid
__device__ float    g_cls[BB * LL];
__device__ float    g_tall[BB * LL][4];
__device__ unsigned g_suppw[BB * SUPPW_PER_B]; // supp bitmask; cleared by k_loss each run

__device__ __forceinline__ int seg_base(int lvl, int a) {
    return (lvl == 0) ? a * 6 : (lvl == 1) ? 18 + a * 22 : 84 + a * 85;
}

__device__ __forceinline__ float bce_term(float y) {
    float sp = fmaxf(y, 0.0f) + __logf(1.0f + __expf(-fabsf(y)));
    return fminf(sp, 100.0f);
}

__device__ __forceinline__ void decode_prior(int n, int& lvl, int& a, int& cell) {
    int rl;
    if (n < 507)       { lvl = 0; rl = n; }
    else if (n < 2535) { lvl = 1; rl = n - 507; }
    else               { lvl = 2; rl = n - 2535; }
    a = rl % 3;
    cell = rl / 3;
}

// pass 1 for one pyramid level using SMEM 1-D overlap tables.
// inter = xlen[la][j] * ylen[la][i] is bitwise-identical to the fused IOU.
template <int LVL, int S, int CNT, int OFF>
__device__ __forceinline__ void pass1_level(
    const float* __restrict__ sxlen, const float* __restrict__ sylen,
    float* __restrict__ sint, int tid, int b, float barea,
    float& na, float& nb) {
    const float area0 = g_T.AREA[LVL * 3 + 0];
    const float area1 = g_T.AREA[LVL * 3 + 1];
    const float area2 = g_T.AREA[LVL * 3 + 2];
    for (int rl = tid; rl < CNT; rl += TT) {
        int a = rl % 3;
        int cell = rl / 3;
        int j = cell % S, i = cell / S;
        int la = LVL * 3 + a;
        float ar = __fmul_rn(sxlen[la * 52 + j], sylen[la * 52 + i]);
        float area = (a == 0) ? area0 : (a == 1) ? area1 : area2;
        float bden = __fsub_rn(__fadd_rn(area, barea), ar);
        sint[OFF + rl] = ar;
        // supp: iou >= 0.5  <=>  ar >= 0.5*bden (exact scale), borderline -> div
        float h = 0.5f * bden;
        bool s = (ar >= h);
        if (!s && ar >= h * 0.9999994f)
            s = (__fdiv_rn(ar, bden) >= 0.5f);
        if (s)
            atomicOr(&g_suppw[b * SUPPW_PER_B + seg_base(LVL, a) + (cell >> 5)],
                     1u << (cell & 31));
        // rational max: ar/bden > na/nb  <=>  ar*nb > na*bden (all positive)
        if (__fmul_rn(ar, nb) > __fmul_rn(na, bden)) { na = ar; nb = bden; }
    }
}

// ---------------------------------------------------------------- targets
// one block per (b,label); 512 threads; separable-IOU, zero global prior traffic
__global__ void __launch_bounds__(TT) k_targets(const float* __restrict__ labels,
                                                float* __restrict__ outp) {
    __shared__ float sint[NPRI];          // intersection areas (exact pass-1 bits)
    __shared__ float sxlen[9 * 52];       // 1-D x-overlap per (la, j)
    __shared__ float sylen[9 * 52];       // 1-D y-overlap per (la, i)
    __shared__ float spair[32];           // per-warp (na, nb)
    __shared__ int   wsum[16];
    __shared__ int   woff[17];
    __shared__ float sm_m;

    int gl  = blockIdx.x;
    int b   = gl / LL;
    int tid = threadIdx.x;
    int lane = tid & 31, wid = tid >> 5;
    const int NW = TT / 32;

    if (gl == 0 && tid < 3) outp[tid] = 0.f;   // zero output for this run

    const float* lab = labels + (size_t)gl * 5;
    float cls = lab[0];
    if (cls < 0.0f) {
        if (tid == 0) g_idx[gl] = -1;
        cudaTriggerProgrammaticLaunchCompletion();
        return;
    }
    float bx = lab[1], by = lab[2], bw = lab[3], bh = lab[4];
    float barea = __fmul_rn(bw, bh);
    float bxe = __fadd_rn(bx, bw);
    float bye = __fadd_rn(by, bh);

    // ---- build 1-D overlap tables (936 entries; bit-identical sub-ops) -----
    for (int t = tid; t < 936; t += TT) {
        int half = t / 468;
        int e = t % 468;
        int la = e / 52, jj = e % 52;
        if (half == 0) {
            float px = g_T.PX[la][jj], pwv = g_T.PW[la];
            float ix = fmaxf(px, bx);
            float ax = fminf(__fadd_rn(px, pwv), bxe);
            sxlen[e] = fmaxf(__fsub_rn(ax, ix), 0.0f);
        } else {
            float py = g_T.PY[la][jj], phv = g_T.PH[la];
            float iy = fmaxf(py, by);
            float ay = fminf(__fadd_rn(py, phv), bye);
            sylen[e] = fmaxf(__fsub_rn(ay, iy), 0.0f);
        }
    }
    __syncthreads();

    // ---- pass 1: smem-product iou into sint; rational max; supp bits -------
    float na = 0.f, nb = 1.f;
    pass1_level<0, 13, 507,  0   >(sxlen, sylen, sint, tid, b, barea, na, nb);
    pass1_level<1, 26, 2028, 507 >(sxlen, sylen, sint, tid, b, barea, na, nb);
    pass1_level<2, 52, 8112, 2535>(sxlen, sylen, sint, tid, b, barea, na, nb);

    #pragma unroll
    for (int o = 16; o > 0; o >>= 1) {
        float oa = __shfl_xor_sync(0xffffffffu, na, o);
        float ob = __shfl_xor_sync(0xffffffffu, nb, o);
        if (__fmul_rn(oa, nb) > __fmul_rn(na, ob)) { na = oa; nb = ob; }
    }
    if (lane == 0) { spair[wid * 2] = na; spair[wid * 2 + 1] = nb; }
    __syncthreads();
    if (tid == 0) {
        na = spair[0]; nb = spair[1];
        #pragma unroll
        for (int w2 = 1; w2 < NW; w2++) {
            float oa = spair[w2 * 2], ob = spair[w2 * 2 + 1];
            if (__fmul_rn(oa, nb) > __fmul_rn(na, ob)) { na = oa; nb = ob; }
        }
        sm_m = (na == 0.f) ? 0.f : __fdiv_rn(na, nb);   // the ONE division
    }
    __syncthreads();
    float m = sm_m;
    float pm = __fmul_rn(m, 0.9999990f);
    bool mzero = (m == 0.f);

    // ---- pass 2: ordered tie count (div only for prefiltered candidates) ---
    int start = tid * CH;
    int end = min(start + CH, NPRI);
    int cnt = 0;
    for (int n = start; n < end; n++) {
        float a = sint[n];
        if (mzero) { if (a == 0.f) cnt++; continue; }
        int lvl = (n < 507) ? 0 : (n < 2535) ? 1 : 2;
        float area = g_T.AREA[lvl * 3 + (n % 3)];
        float bden = __fsub_rn(__fadd_rn(area, barea), a);
        if (a >= __fmul_rn(pm, bden))
            if (__fdiv_rn(a, bden) == m) cnt++;
    }

    int inc = cnt;
    #pragma unroll
    for (int o = 1; o < 32; o <<= 1) {
        int v = __shfl_up_sync(0xffffffffu, inc, o);
        if (lane >= o) inc += v;
    }
    if (lane == 31) wsum[wid] = inc;
    __syncthreads();
    if (tid == 0) {
        int r = 0;
        #pragma unroll
        for (int w2 = 0; w2 < NW; w2++) { woff[w2] = r; r += wsum[w2]; }
        woff[NW] = r;
    }
    __syncthreads();
    int excl = woff[wid] + inc - cnt;
    int k = woff[NW];
    int rank = (k - 1) / 2 + 1;

    if (excl < rank && rank <= excl + cnt) {
        int need = rank - excl;
        int idx = -1;
        for (int n = start; n < end; n++) {
            float a = sint[n];
            bool tie;
            if (mzero) tie = (a == 0.f);
            else {
                int lvl = (n < 507) ? 0 : (n < 2535) ? 1 : 2;
                float area = g_T.AREA[lvl * 3 + (n % 3)];
                float bden = __fsub_rn(__fadd_rn(area, barea), a);
                tie = (a >= __fmul_rn(pm, bden)) && (__fdiv_rn(a, bden) == m);
            }
            if (tie && --need == 0) { idx = n; break; }
        }
        const float* aux = g_P.aux[idx];
        float Sf = (idx < 507) ? 13.f : (idx < 2535) ? 26.f : 52.f;
        float dx = fminf(fmaxf((bx + 0.5f * bw) * Sf - aux[0], 1e-6f), 0.999999f);
        float dy = fminf(fmaxf((by + 0.5f * bh) * Sf - aux[1], 1e-6f), 0.999999f);
        g_tall[gl][0] = logf(dx / (1.0f - dx));
        g_tall[gl][1] = logf(dy / (1.0f - dy));
        g_tall[gl][2] = logf(bw * 416.0f / aux[2]);
        g_tall[gl][3] = logf(bh * 416.0f / aux[3]);
        g_cls[gl] = cls;
        g_idx[gl] = idx;
    }
    cudaTriggerProgrammaticLaunchCompletion();
}

// ---------------------------------------------------------------- loss
// grid = BB*45; each block: fixed (b, lvl, a), 256 consecutive cells.
// PDL: obj-channel input load issued BEFORE the grid-dependency sync.
// Each block atomicAdds its 3 normalized partials directly to outp.
__global__ void __launch_bounds__(256) k_loss(const float* __restrict__ o0,
                                              const float* __restrict__ o1,
                                              const float* __restrict__ o2,
                                              float* __restrict__ outp) {
    __shared__ float    sacc[3];            // obj, coord, cls partial (this block's lvl)
    __shared__ int      swin[256];          // winning label per local cell, -1 none
    __shared__ unsigned smask[256][3];      // class bitmask per local cell

    int b = blockIdx.x / BLKS_PER_B;
    int r = blockIdx.x % BLKS_PER_B;
    int tid = threadIdx.x;

    int lvl, a, c0, nc;
    if (r < 3)       { lvl = 0; a = r;            c0 = 0;               nc = 169; }
    else if (r < 12) { int q = r - 3;  lvl = 1; a = q / 3;  int bi = q % 3;
                       c0 = bi * 256; nc = (bi < 2) ? 256 : 676 - 512; }
    else             { int q = r - 12; lvl = 2; a = q / 11; int bi = q % 11;
                       c0 = bi * 256; nc = (bi < 10) ? 256 : 2704 - 2560; }

    int cell = c0 + tid;
    bool active = tid < nc;

    int SS_ = (lvl == 0) ? 169 : (lvl == 1) ? 676 : 2704;
    const float* out = (lvl == 0) ? o0 : (lvl == 1) ? o1 : o2;
    const float* base0 = out + (size_t)b * 255 * SS_ + (size_t)a * 85 * SS_ + cell;

    // ---- independent prelude: smem init + obj input load (overlaps producer)
    if (tid < 3) sacc[tid] = 0.f;
    swin[tid] = -1;
    smask[tid][0] = 0u; smask[tid][1] = 0u; smask[tid][2] = 0u;
    float xobj = 0.f;
    if (active) xobj = base0[4 * SS_];     // input data: NOT produced by k_targets

    // ---- wait for k_targets' state writes ----------------------------------
    cudaGridDependencySynchronize();
    __syncthreads();

    // mark chosen cells belonging to this block (O(LL) work)
    if (tid < LL) {
        int gl = b * LL + tid;
        int idx = __ldcg(&g_idx[gl]);
        if (idx >= 0) {
            int le, ae, ce;
            decode_prior(idx, le, ae, ce);
            if (le == lvl && ae == a && ce >= c0 && ce < c0 + nc) {
                int c = ce - c0;
                atomicMax(&swin[c], tid);
                int ci = (int)__ldcg(&g_cls[gl]);
                atomicOr(&smask[c][ci >> 5], 1u << (ci & 31));
            }
        }
    }
    __syncthreads();

    bool chosen = false;
    int wlab = -1;
    float objc = 0.f;

    if (active) {
        unsigned word = g_suppw[b * SUPPW_PER_B + seg_base(lvl, a) + (cell >> 5)];
        bool supp = (word >> (cell & 31)) & 1u;
        wlab = swin[tid];
        chosen = (wlab >= 0);
        if (chosen || !supp)
            objc = bce_term(chosen ? -xobj : xobj);
    }
    #pragma unroll
    for (int o = 16; o > 0; o >>= 1)
        objc += __shfl_xor_sync(0xffffffffu, objc, o);
    if ((tid & 31) == 0 && objc != 0.f) atomicAdd(&sacc[0], objc);

    // warp-cooperative handling of chosen priors
    unsigned cmask = __ballot_sync(0xffffffffu, chosen);
    int myl = tid & 31;
    while (cmask) {
        int src = __ffs(cmask) - 1;
        cmask &= cmask - 1;
        unsigned long long bp = __shfl_sync(0xffffffffu, (unsigned long long)base0, src);
        const float* cb = (const float*)bp;
        int clab = __shfl_sync(0xffffffffu, wlab, src);
        int cloc = __shfl_sync(0xffffffffu, tid, src);

        float csum = 0.f;
        if (myl < 4) {
            float d = cb[myl * SS_] - __ldcg(&g_tall[b * LL + clab][myl]);
            csum = d * d;
        }
        float ksum = 0.f;
        #pragma unroll
        for (int kb = 0; kb < 3; kb++) {
            int k = myl + kb * 32;
            if (k < NCLS) {
                float x = cb[(5 + k) * SS_];
                unsigned mw = smask[cloc][k >> 5];
                bool bit = (mw >> (k & 31)) & 1u;
                ksum += bce_term(bit ? -x : x);
            }
        }
        #pragma unroll
        for (int o = 16; o > 0; o >>= 1) {
            csum += __shfl_xor_sync(0xffffffffu, csum, o);
            ksum += __shfl_xor_sync(0xffffffffu, ksum, o);
        }
        if (myl == 0) {
            atomicAdd(&sacc[1], csum);
            atomicAdd(&sacc[2], ksum);
        }
    }

    __syncthreads();                       // sacc complete; supp words all read
    // clear this block's supp words for the next graph replay
    if (active && (tid & 31) == 0)
        g_suppw[b * SUPPW_PER_B + seg_base(lvl, a) + (cell >> 5)] = 0u;

    // direct normalized accumulation into outp (no fence / final block needed)
    if (tid < 3) {
        float v = sacc[tid];
        if (v != 0.f) {
            float ssf = (lvl == 0) ? 169.f : (lvl == 1) ? 676.f : 2704.f;
            float den = ssf * ((tid == 0) ? 48.f : (tid == 1) ? 192.f : 3840.f);
            atomicAdd(&outp[tid], v / den);
        }
    }
}

// ---------------------------------------------------------------- launch
extern "C" void kernel_launch(void* const* d_in, const int* in_sizes, int n_in,
                              void* d_out, int out_size) {
    const float *o0 = nullptr, *o1 = nullptr, *o2 = nullptr, *lab = nullptr;
    for (int i = 0; i < n_in; i++) {
        switch (in_sizes[i]) {
            case 16 * 255 * 13 * 13: o0 = (const float*)d_in[i]; break;
            case 16 * 255 * 26 * 26: o1 = (const float*)d_in[i]; break;
            case 16 * 255 * 52 * 52: o2 = (const float*)d_in[i]; break;
            case 16 * 1 * 50 * 5:    lab = (const float*)d_in[i]; break;
            default: break;
        }
    }
    if (!o0 || !o1 || !o2 || !lab) {
        o0 = (const float*)d_in[0];
        o1 = (const float*)d_in[1];
        o2 = (const float*)d_in[2];
        lab = (const float*)d_in[3];
    }

    k_targets<<<BB * LL, TT>>>(lab, (float*)d_out);

    // k_loss with programmatic dependent launch
    cudaLaunchConfig_t cfg = {};
    cfg.gridDim  = dim3(BB * BLKS_PER_B, 1, 1);
    cfg.blockDim = dim3(256, 1, 1);
    cfg.dynamicSmemBytes = 0;
    cfg.stream = 0;
    cudaLaunchAttribute attrs[1];
    attrs[0].id = cudaLaunchAttributeProgrammaticStreamSerialization;
    attrs[0].val.programmaticStreamSerializationAllowed = 1;
    cfg.attrs = attrs;
    cfg.numAttrs = 1;
    cudaError_t e = cudaLaunchKernelEx(&cfg, k_loss, o0, o1, o2, (float*)d_out);
    if (e != cudaSuccess) {
        k_loss<<<BB * BLKS_PER_B, 256>>>(o0, o1, o2, (float*)d_out);
    }
}

// round 14
// speedup vs baseline: 1.1724x; 1.1724x over previous
#include <cuda_runtime.h>
#include <math.h>

#define NPRI  10647
#define BB    16
#define LL    50
#define NCLS  80
#define BLKS_PER_B 45      // lvl0: 3 blocks, lvl1: 9, lvl2: 33 (cell-contiguous per anchor)
#define SUPPW_PER_B 339    // 3*(6+22+85) words, segments padded per (lvl,a)
#define TT 512             // k_targets block size
#define CH 21              // ceil(10647/512)

// ---------------- compile-time priors (double math -> f32, matches numpy) ----
struct alignas(16) Priors {
    float aux[NPRI][4];   // col(j), row(i), aw_pix, ah_pix  (winner decode only)
};

constexpr Priors mk_priors() {
    Priors t{};
    const int AW[3][3] = {{116, 156, 373}, {30, 62, 59}, {10, 16, 33}};
    const int AH[3][3] = {{90, 198, 326}, {61, 45, 119}, {13, 30, 23}};
    const int SSv[3] = {13, 26, 52};
    int n = 0;
    for (int l = 0; l < 3; l++) {
        int S = SSv[l];
        for (int i = 0; i < S; i++)
            for (int j = 0; j < S; j++)
                for (int a = 0; a < 3; a++) {
                    t.aux[n][0] = (float)j;
                    t.aux[n][1] = (float)i;
                    t.aux[n][2] = (float)AW[l][a];
                    t.aux[n][3] = (float)AH[l][a];
                    n++;
                }
    }
    return t;
}
__device__ constexpr Priors g_P = mk_priors();

// factored prior geometry: px/py per (lvl*3+a, j), pw/ph/area per (lvl*3+a)
struct PriorTabs {
    float PX[9][52];   // cx - 0.5*w  (f64 math -> f32, matches numpy bits)
    float PY[9][52];   // cy - 0.5*h
    float PW[9];
    float PH[9];
    float AREA[9];     // f32(w)*f32(h) == __fmul_rn(pw, ph)
};

constexpr PriorTabs mk_tabs() {
    PriorTabs t{};
    const int AW[3][3] = {{116, 156, 373}, {30, 62, 59}, {10, 16, 33}};
    const int AH[3][3] = {{90, 198, 326}, {61, 45, 119}, {13, 30, 23}};
    const int SSv[3] = {13, 26, 52};
    for (int l = 0; l < 3; l++) {
        int S = SSv[l];
        for (int a = 0; a < 3; a++) {
            int la = l * 3 + a;
            double w = AW[l][a] / 416.0;
            double h = AH[l][a] / 416.0;
            t.PW[la] = (float)w;
            t.PH[la] = (float)h;
            t.AREA[la] = (float)w * (float)h;
            for (int j = 0; j < S; j++) {
                t.PX[la][j] = (float)((j + 0.5) / (double)S - 0.5 * w);
                t.PY[la][j] = (float)((j + 0.5) / (double)S - 0.5 * h);
            }
        }
    }
    return t;
}
__device__ constexpr PriorTabs g_T = mk_tabs();

// ---------------- compact cross-kernel state -------------------------------
__device__ int      g_idx[BB * LL];            // chosen prior per (b,label), -1 invalid
__device__ float    g_cls[BB * LL];
__device__ float    g_tall[BB * LL][4];
__device__ unsigned g_suppw[BB * SUPPW_PER_B]; // supp bitmask; cleared by k_loss each run

__device__ __forceinline__ int seg_base(int lvl, int a) {
    return (lvl == 0) ? a * 6 : (lvl == 1) ? 18 + a * 22 : 84 + a * 85;
}

__device__ __forceinline__ float bce_term(float y) {
    float sp = fmaxf(y, 0.0f) + __logf(1.0f + __expf(-fabsf(y)));
    return fminf(sp, 100.0f);
}

__device__ __forceinline__ void decode_prior(int n, int& lvl, int& a, int& cell) {
    int rl;
    if (n < 507)       { lvl = 0; rl = n; }
    else if (n < 2535) { lvl = 1; rl = n - 507; }
    else               { lvl = 2; rl = n - 2535; }
    a = rl % 3;
    cell = rl / 3;
}

// pass 1 for one level: per-CELL iteration, 3-anchor unroll.
// inter = xlen[la][j]*ylen[la][i] is bitwise-identical to the fused IOU
// (validated in R13). Decode cost: 2 constant-divisor IMADs per 3 priors.
template <int LVL, int S, int OFF>
__device__ __forceinline__ void pass1_level(
    const float* __restrict__ sxlen, const float* __restrict__ sylen,
    float* __restrict__ sint, int tid, int b, float barea,
    float& na, float& nb) {
    for (int c = tid; c < S * S; c += TT) {
        int j = c % S, i = c / S;          // constant divisors
        #pragma unroll
        for (int a = 0; a < 3; a++) {
            const int la = LVL * 3 + a;
            float ar = __fmul_rn(sxlen[la * 52 + j], sylen[la * 52 + i]);
            float bden = __fsub_rn(__fadd_rn(g_T.AREA[la], barea), ar);
            sint[OFF + c * 3 + a] = ar;
            // supp: iou >= 0.5  <=>  ar >= 0.5*bden; rare borderline -> div
            float h = 0.5f * bden;
            bool s = (ar >= h);
            if (!s && ar >= h * 0.9999994f)
                s = (__fdiv_rn(ar, bden) >= 0.5f);
            if (s)
                atomicOr(&g_suppw[b * SUPPW_PER_B + seg_base(LVL, a) + (c >> 5)],
                         1u << (c & 31));
            // rational max: ar/bden > na/nb  <=>  ar*nb > na*bden (all positive)
            if (__fmul_rn(ar, nb) > __fmul_rn(na, bden)) { na = ar; nb = bden; }
        }
    }
}

// ---------------------------------------------------------------- targets
// one block per (b,label); 512 threads; separable IOU with per-cell decode
__global__ void __launch_bounds__(TT) k_targets(const float* __restrict__ labels,
                                                float* __restrict__ outp) {
    __shared__ float sint[NPRI];          // intersection areas (exact pass-1 bits)
    __shared__ float sxlen[9 * 52];       // 1-D x-overlap per (la, j)
    __shared__ float sylen[9 * 52];       // 1-D y-overlap per (la, i)
    __shared__ float spair[32];           // per-warp (na, nb)
    __shared__ int   wsum[16];
    __shared__ int   woff[17];
    __shared__ float sm_m;

    int gl  = blockIdx.x;
    int b   = gl / LL;
    int tid = threadIdx.x;
    int lane = tid & 31, wid = tid >> 5;
    const int NW = TT / 32;

    if (gl == 0 && tid < 3) outp[tid] = 0.f;   // zero output for this run

    const float* lab = labels + (size_t)gl * 5;
    float cls = lab[0];
    if (cls < 0.0f) {
        if (tid == 0) g_idx[gl] = -1;
        cudaTriggerProgrammaticLaunchCompletion();
        return;
    }
    float bx = lab[1], by = lab[2], bw = lab[3], bh = lab[4];
    float barea = __fmul_rn(bw, bh);
    float bxe = __fadd_rn(bx, bw);
    float bye = __fadd_rn(by, bh);

    // ---- build 1-D overlap tables (936 entries; bit-identical sub-ops) -----
    if (tid < 468) {
        int la = tid / 52, jj = tid % 52;
        float px = g_T.PX[la][jj], pwv = g_T.PW[la];
        float ix = fmaxf(px, bx);
        float ax = fminf(__fadd_rn(px, pwv), bxe);
        sxlen[tid] = fmaxf(__fsub_rn(ax, ix), 0.0f);
        float py = g_T.PY[la][jj], phv = g_T.PH[la];
        float iy = fmaxf(py, by);
        float ay = fminf(__fadd_rn(py, phv), bye);
        sylen[tid] = fmaxf(__fsub_rn(ay, iy), 0.0f);
    }
    __syncthreads();

    // ---- pass 1: per-cell separable iou; rational max; supp bits -----------
    float na = 0.f, nb = 1.f;
    pass1_level<0, 13, 0   >(sxlen, sylen, sint, tid, b, barea, na, nb);
    pass1_level<1, 26, 507 >(sxlen, sylen, sint, tid, b, barea, na, nb);
    pass1_level<2, 52, 2535>(sxlen, sylen, sint, tid, b, barea, na, nb);

    #pragma unroll
    for (int o = 16; o > 0; o >>= 1) {
        float oa = __shfl_xor_sync(0xffffffffu, na, o);
        float ob = __shfl_xor_sync(0xffffffffu, nb, o);
        if (__fmul_rn(oa, nb) > __fmul_rn(na, ob)) { na = oa; nb = ob; }
    }
    if (lane == 0) { spair[wid * 2] = na; spair[wid * 2 + 1] = nb; }
    __syncthreads();
    if (tid == 0) {
        na = spair[0]; nb = spair[1];
        #pragma unroll
        for (int w2 = 1; w2 < NW; w2++) {
            float oa = spair[w2 * 2], ob = spair[w2 * 2 + 1];
            if (__fmul_rn(oa, nb) > __fmul_rn(na, ob)) { na = oa; nb = ob; }
        }
        sm_m = (na == 0.f) ? 0.f : __fdiv_rn(na, nb);   // the ONE division
    }
    __syncthreads();
    float m = sm_m;
    float pm = __fmul_rn(m, 0.9999990f);
    bool mzero = (m == 0.f);

    // ---- pass 2: ordered tie count (div only for prefiltered candidates) ---
    int start = tid * CH;
    int end = min(start + CH, NPRI);
    int cnt = 0;
    for (int n = start; n < end; n++) {
        float a = sint[n];
        if (mzero) { if (a == 0.f) cnt++; continue; }
        int lvl = (n < 507) ? 0 : (n < 2535) ? 1 : 2;
        float area = g_T.AREA[lvl * 3 + (n % 3)];
        float bden = __fsub_rn(__fadd_rn(area, barea), a);
        if (a >= __fmul_rn(pm, bden))
            if (__fdiv_rn(a, bden) == m) cnt++;
    }

    int inc = cnt;
    #pragma unroll
    for (int o = 1; o < 32; o <<= 1) {
        int v = __shfl_up_sync(0xffffffffu, inc, o);
        if (lane >= o) inc += v;
    }
    if (lane == 31) wsum[wid] = inc;
    __syncthreads();
    if (tid == 0) {
        int r = 0;
        #pragma unroll
        for (int w2 = 0; w2 < NW; w2++) { woff[w2] = r; r += wsum[w2]; }
        woff[NW] = r;
    }
    __syncthreads();
    int excl = woff[wid] + inc - cnt;
    int k = woff[NW];
    int rank = (k - 1) / 2 + 1;

    if (excl < rank && rank <= excl + cnt) {
        int need = rank - excl;
        int idx = -1;
        for (int n = start; n < end; n++) {
            float a = sint[n];
            bool tie;
            if (mzero) tie = (a == 0.f);
            else {
                int lvl = (n < 507) ? 0 : (n < 2535) ? 1 : 2;
                float area = g_T.AREA[lvl * 3 + (n % 3)];
                float bden = __fsub_rn(__fadd_rn(area, barea), a);
                tie = (a >= __fmul_rn(pm, bden)) && (__fdiv_rn(a, bden) == m);
            }
            if (tie && --need == 0) { idx = n; break; }
        }
        const float* aux = g_P.aux[idx];
        float Sf = (idx < 507) ? 13.f : (idx < 2535) ? 26.f : 52.f;
        float dx = fminf(fmaxf((bx + 0.5f * bw) * Sf - aux[0], 1e-6f), 0.999999f);
        float dy = fminf(fmaxf((by + 0.5f * bh) * Sf - aux[1], 1e-6f), 0.999999f);
        g_tall[gl][0] = logf(dx / (1.0f - dx));
        g_tall[gl][1] = logf(dy / (1.0f - dy));
        g_tall[gl][2] = logf(bw * 416.0f / aux[2]);
        g_tall[gl][3] = logf(bh * 416.0f / aux[3]);
        g_cls[gl] = cls;
        g_idx[gl] = idx;
    }
    cudaTriggerProgrammaticLaunchCompletion();
}

// ---------------------------------------------------------------- loss
// grid = BB*45; each block: fixed (b, lvl, a), 256 consecutive cells.
// PDL: obj-channel input load issued BEFORE the grid-dependency sync.
// Each block atomicAdds its 3 normalized partials directly to outp.
__global__ void __launch_bounds__(256) k_loss(const float* __restrict__ o0,
                                              const float* __restrict__ o1,
                                              const float* __restrict__ o2,
                                              float* __restrict__ outp) {
    __shared__ float    sacc[3];            // obj, coord, cls partial (this block's lvl)
    __shared__ int      swin[256];          // winning label per local cell, -1 none
    __shared__ unsigned smask[256][3];      // class bitmask per local cell

    int b = blockIdx.x / BLKS_PER_B;
    int r = blockIdx.x % BLKS_PER_B;
    int tid = threadIdx.x;

    int lvl, a, c0, nc;
    if (r < 3)       { lvl = 0; a = r;            c0 = 0;               nc = 169; }
    else if (r < 12) { int q = r - 3;  lvl = 1; a = q / 3;  int bi = q % 3;
                       c0 = bi * 256; nc = (bi < 2) ? 256 : 676 - 512; }
    else             { int q = r - 12; lvl = 2; a = q / 11; int bi = q % 11;
                       c0 = bi * 256; nc = (bi < 10) ? 256 : 2704 - 2560; }

    int cell = c0 + tid;
    bool active = tid < nc;

    int SS_ = (lvl == 0) ? 169 : (lvl == 1) ? 676 : 2704;
    const float* out = (lvl == 0) ? o0 : (lvl == 1) ? o1 : o2;
    const float* base0 = out + (size_t)b * 255 * SS_ + (size_t)a * 85 * SS_ + cell;

    // ---- independent prelude: smem init + obj input load (overlaps producer)
    if (tid < 3) sacc[tid] = 0.f;
    swin[tid] = -1;
    smask[tid][0] = 0u; smask[tid][1] = 0u; smask[tid][2] = 0u;
    float xobj = 0.f;
    if (active) xobj = base0[4 * SS_];     // input data: NOT produced by k_targets

    // ---- wait for k_targets' state writes ----------------------------------
    cudaGridDependencySynchronize();
    __syncthreads();

    // mark chosen cells belonging to this block (O(LL) work)
    if (tid < LL) {
        int gl = b * LL + tid;
        int idx = __ldcg(&g_idx[gl]);
        if (idx >= 0) {
            int le, ae, ce;
            decode_prior(idx, le, ae, ce);
            if (le == lvl && ae == a && ce >= c0 && ce < c0 + nc) {
                int c = ce - c0;
                atomicMax(&swin[c], tid);
                int ci = (int)__ldcg(&g_cls[gl]);
                atomicOr(&smask[c][ci >> 5], 1u << (ci & 31));
            }
        }
    }
    __syncthreads();

    bool chosen = false;
    int wlab = -1;
    float objc = 0.f;

    if (active) {
        unsigned word = g_suppw[b * SUPPW_PER_B + seg_base(lvl, a) + (cell >> 5)];
        bool supp = (word >> (cell & 31)) & 1u;
        wlab = swin[tid];
        chosen = (wlab >= 0);
        if (chosen || !supp)
            objc = bce_term(chosen ? -xobj : xobj);
    }
    #pragma unroll
    for (int o = 16; o > 0; o >>= 1)
        objc += __shfl_xor_sync(0xffffffffu, objc, o);
    if ((tid & 31) == 0 && objc != 0.f) atomicAdd(&sacc[0], objc);

    // warp-cooperative handling of chosen priors
    unsigned cmask = __ballot_sync(0xffffffffu, chosen);
    int myl = tid & 31;
    while (cmask) {
        int src = __ffs(cmask) - 1;
        cmask &= cmask - 1;
        unsigned long long bp = __shfl_sync(0xffffffffu, (unsigned long long)base0, src);
        const float* cb = (const float*)bp;
        int clab = __shfl_sync(0xffffffffu, wlab, src);
        int cloc = __shfl_sync(0xffffffffu, tid, src);

        float csum = 0.f;
        if (myl < 4) {
            float d = cb[myl * SS_] - __ldcg(&g_tall[b * LL + clab][myl]);
            csum = d * d;
        }
        float ksum = 0.f;
        #pragma unroll
        for (int kb = 0; kb < 3; kb++) {
            int k = myl + kb * 32;
            if (k < NCLS) {
                float x = cb[(5 + k) * SS_];
                unsigned mw = smask[cloc][k >> 5];
                bool bit = (mw >> (k & 31)) & 1u;
                ksum += bce_term(bit ? -x : x);
            }
        }
        #pragma unroll
        for (int o = 16; o > 0; o >>= 1) {
            csum += __shfl_xor_sync(0xffffffffu, csum, o);
            ksum += __shfl_xor_sync(0xffffffffu, ksum, o);
        }
        if (myl == 0) {
            atomicAdd(&sacc[1], csum);
            atomicAdd(&sacc[2], ksum);
        }
    }

    __syncthreads();                       // sacc complete; supp words all read
    // clear this block's supp words for the next graph replay
    if (active && (tid & 31) == 0)
        g_suppw[b * SUPPW_PER_B + seg_base(lvl, a) + (cell >> 5)] = 0u;

    // direct normalized accumulation into outp (no fence / final block needed)
    if (tid < 3) {
        float v = sacc[tid];
        if (v != 0.f) {
            float ssf = (lvl == 0) ? 169.f : (lvl == 1) ? 676.f : 2704.f;
            float den = ssf * ((tid == 0) ? 48.f : (tid == 1) ? 192.f : 3840.f);
            atomicAdd(&outp[tid], v / den);
        }
    }
}

// ---------------------------------------------------------------- launch
extern "C" void kernel_launch(void* const* d_in, const int* in_sizes, int n_in,
                              void* d_out, int out_size) {
    const float *o0 = nullptr, *o1 = nullptr, *o2 = nullptr, *lab = nullptr;
    for (int i = 0; i < n_in; i++) {
        switch (in_sizes[i]) {
            case 16 * 255 * 13 * 13: o0 = (const float*)d_in[i]; break;
            case 16 * 255 * 26 * 26: o1 = (const float*)d_in[i]; break;
            case 16 * 255 * 52 * 52: o2 = (const float*)d_in[i]; break;
            case 16 * 1 * 50 * 5:    lab = (const float*)d_in[i]; break;
            default: break;
        }
    }
    if (!o0 || !o1 || !o2 || !lab) {
        o0 = (const float*)d_in[0];
        o1 = (const float*)d_in[1];
        o2 = (const float*)d_in[2];
        lab = (const float*)d_in[3];
    }

    k_targets<<<BB * LL, TT>>>(lab, (float*)d_out);

    // k_loss with programmatic dependent launch
    cudaLaunchConfig_t cfg = {};
    cfg.gridDim  = dim3(BB * BLKS_PER_B, 1, 1);
    cfg.blockDim = dim3(256, 1, 1);
    cfg.dynamicSmemBytes = 0;
    cfg.stream = 0;
    cudaLaunchAttribute attrs[1];
    attrs[0].id = cudaLaunchAttributeProgrammaticStreamSerialization;
    attrs[0].val.programmaticStreamSerializationAllowed = 1;
    cfg.attrs = attrs;
    cfg.numAttrs = 1;
    cudaError_t e = cudaLaunchKernelEx(&cfg, k_loss, o0, o1, o2, (float*)d_out);
    if (e != cudaSuccess) {
        k_loss<<<BB * BLKS_PER_B, 256>>>(o0, o1, o2, (float*)d_out);
    }
}